// round 9
// baseline (speedup 1.0000x reference)
#include <cuda_runtime.h>

// Problem constants (shapes fixed by dataset; code stays correct for any
// batch_list via the offsets kernel + generic path).
#define D_DIM   300          // embedding dim
#define DC      60           // columns per chunk (multiple of 4, divides 300)
#define DC4     (DC / 4)     // 15 float4 per row-chunk
#define NCHUNK  (D_DIM / DC) // 5
#define TR      256          // row tile (== nodes per graph in this dataset)
#define RB      32           // row-blocks
#define NT      (RB * DC4)   // 480 threads per CTA
#define KIT     (TR / RB)    // 8 rows per thread in fast path
#define TILE4   (TR * DC4)   // 3840 float4 per tile buffer
#define MAXB    8192
#define EPSV    1e-12f

// Scratch (no cudaMalloc allowed): per-graph row offsets + actual graph count.
__device__ int g_off[MAXB + 1];
__device__ int g_B;

// ---------------------------------------------------------------------------
// cp.async helpers
// ---------------------------------------------------------------------------
__device__ __forceinline__ void cp_async16(unsigned smem_addr, const void* gptr) {
    asm volatile("cp.async.cg.shared.global [%0], [%1], 16;"
                 :: "r"(smem_addr), "l"(gptr));
}
__device__ __forceinline__ void cp_commit() {
    asm volatile("cp.async.commit_group;");
}
__device__ __forceinline__ void cp_wait_all() {
    asm volatile("cp.async.wait_group 0;");
}

// ---------------------------------------------------------------------------
// Offsets kernel: detects int32 vs int64 batch_list layout. Fast path: if all
// counts are equal (dataset case), writes offsets arithmetically with no scan.
// Fallback: block-wide inclusive scan.
// ---------------------------------------------------------------------------
__global__ void offsets_kernel(const int* __restrict__ p32, int nb, int ntot) {
    __shared__ int sh[1024];
    __shared__ int s_stride, s_carry, s_uni, s_val;
    const int tid = threadIdx.x;

    if (tid == 0) {
        int stride = 1;
        if (nb > 1) {
            int v0 = p32[0], v1 = p32[1];
            if (v1 == 0 && v0 != 0) stride = 2;   // int64 little-endian
        }
        s_stride = stride;
        s_carry = 0;
        s_uni = 1;
        s_val = p32[0];
        g_off[0] = 0;
    }
    __syncthreads();

    const int st = s_stride;
    int B = nb;
    if (B > MAXB) B = MAXB;
    const int B1 = (st == 2) ? (B >> 1) : B;
    const int v0 = s_val;

    int uni = 1;
    for (int i = tid; i < B1; i += 1024)
        if (p32[(size_t)i * st] != v0) uni = 0;
    if (!uni) atomicAnd(&s_uni, 0);
    __syncthreads();

    if (s_uni && (long long)B1 * v0 == ntot) {
        for (int i = tid; i < B1; i += 1024)
            g_off[i + 1] = (i + 1) * v0;
        if (tid == 0) g_B = B1;
        return;
    }

    for (int base = 0; base < B1; base += 1024) {
        int i = base + tid;
        int v = (i < B1) ? p32[(size_t)i * st] : 0;
        sh[tid] = v;
        __syncthreads();
        #pragma unroll
        for (int o = 1; o < 1024; o <<= 1) {
            int t = (tid >= o) ? sh[tid - o] : 0;
            __syncthreads();
            sh[tid] += t;
            __syncthreads();
        }
        if (i < B1) g_off[i + 1] = s_carry + sh[tid];
        __syncthreads();
        if (tid == 0) s_carry += sh[1023];
        __syncthreads();
    }

    int Bfinal = B1;
    if (st == 2 && B1 > 0 && g_off[B1] != ntot && B > B1) {
        for (int base = B1; base < B; base += 1024) {
            int i = base + tid;
            int v = (i < B) ? p32[(size_t)i * st] : 0;
            sh[tid] = v;
            __syncthreads();
            #pragma unroll
            for (int o = 1; o < 1024; o <<= 1) {
                int t = (tid >= o) ? sh[tid - o] : 0;
                __syncthreads();
                sh[tid] += t;
                __syncthreads();
            }
            if (i < B) g_off[i + 1] = s_carry + sh[tid];
            __syncthreads();
            if (tid == 0) s_carry += sh[1023];
            __syncthreads();
        }
        Bfinal = B;
    }
    if (tid == 0) g_B = Bfinal;
}

// ---------------------------------------------------------------------------
// Helpers
// ---------------------------------------------------------------------------
__device__ __forceinline__ float4 min4(float4 a, float4 b) {
    return make_float4(fminf(a.x, b.x), fminf(a.y, b.y),
                       fminf(a.z, b.z), fminf(a.w, b.w));
}
__device__ __forceinline__ float4 max4(float4 a, float4 b) {
    return make_float4(fmaxf(a.x, b.x), fmaxf(a.y, b.y),
                       fmaxf(a.z, b.z), fmaxf(a.w, b.w));
}

// ---------------------------------------------------------------------------
// Main kernel: persistent 1 CTA/SM, 480 threads, double-buffered cp.async
// (LDGSTS) pipeline over (graph, 60-col chunk) tiles. While the CTA reduces/
// folds/normalizes tile T from smem buffer s, the async engine is already
// filling buffer s^1 with tile T+1 — no registers spent on prefetch, so the
// DRAM read stream never drains across the barrier/fold phase. Single DRAM
// read + single DRAM write of the tensor.
// ---------------------------------------------------------------------------
__global__ void __launch_bounds__(NT, 1)
cube_norm_kernel(const float* __restrict__ x, float* __restrict__ y,
                 int ntiles) {
    extern __shared__ float4 sm4[];
    float4* buf[2] = { sm4, sm4 + TILE4 };          // 2 x 61440 B
    float*  pmn_s  = (float*)(sm4 + 2 * TILE4);     // 32*60 floats (7680 B)
    float*  pmx_s  = pmn_s + RB * DC;               // 7680 B
    float*  smid   = pmx_s + RB * DC;               // 60 floats
    float*  sinv   = smid + DC;                     // 60 floats

    const int tid = threadIdx.x;
    const int j   = tid % DC4;         // column quad 0..14
    const int rb  = tid / DC4;         // row block 0..31
    const int B   = g_B;
    const int stride = gridDim.x;
    const size_t toff = (size_t)rb * D_DIM + 4 * j;  // thread offset in tile

    // smem byte addresses for this thread's 8 cp.async destinations
    unsigned sbase = (unsigned)__cvta_generic_to_shared(sm4);
    const unsigned tdst = sbase + tid * 16u;

    // ---- tile-descriptor helper state ----
    int t = blockIdx.x;
    bool fast = false;
    int nr_cur = 0;
    size_t off = 0;
    if (t < ntiles) {
        int g = t / NCHUNK;
        if (g >= B) return;
        int r0 = g_off[g];
        nr_cur = g_off[g + 1] - r0;
        off = (size_t)r0 * D_DIM + (t - g * NCHUNK) * DC + toff;
        fast = (nr_cur == TR);
    } else {
        return;
    }

    // ---- prologue: kick off tile 0's loads into buffer 0 ----
    if (fast) {
        const float* p = x + off;
        #pragma unroll
        for (int k = 0; k < KIT; k++)
            cp_async16(tdst + (unsigned)(k * NT * 16), p + (size_t)k * RB * D_DIM);
    }
    cp_commit();

    int it = 0;
    while (t < ntiles) {
        const int s = it & 1;

        // ---- next tile descriptor ----
        int tn = t + stride;
        bool nfast = false;
        int nnr = 0;
        size_t noff = 0;
        if (tn < ntiles) {
            int gn = tn / NCHUNK;
            if (gn >= B) {
                tn = ntiles;                      // uniform exit next iter
            } else {
                int r0n = g_off[gn];
                nnr = g_off[gn + 1] - r0n;
                noff = (size_t)r0n * D_DIM + (tn - gn * NCHUNK) * DC + toff;
                nfast = (nnr == TR);
            }
        }

        // ---- wait for tile t's data; fence prior iter's buffer reads ----
        cp_wait_all();
        __syncthreads();

        // ---- issue tile t+1's loads into the other buffer ----
        if (nfast) {
            const float* pn = x + noff;
            const unsigned dstn = tdst + (unsigned)((s ^ 1) * TILE4 * 16);
            #pragma unroll
            for (int k = 0; k < KIT; k++)
                cp_async16(dstn + (unsigned)(k * NT * 16),
                           pn + (size_t)k * RB * D_DIM);
        }
        cp_commit();

        if (fast) {
            const float4* tb = buf[s];
            // ---- reduce tile t from smem ----
            float4 mn, mx;
            {
                float4 a = tb[tid];
                mn = a; mx = a;
            }
            #pragma unroll
            for (int k = 1; k < KIT; k++) {
                float4 a = tb[k * NT + tid];
                mn = min4(mn, a);
                mx = max4(mx, a);
            }
            *(float4*)&pmn_s[rb * DC + 4 * j] = mn;
            *(float4*)&pmx_s[rb * DC + 4 * j] = mx;
            __syncthreads();

            // ---- fold: 60 threads, one scalar column each ----
            if (tid < DC) {
                float fmn = pmn_s[tid];
                float fmx = pmx_s[tid];
                #pragma unroll
                for (int r = 1; r < RB; r++) {
                    fmn = fminf(fmn, pmn_s[r * DC + tid]);
                    fmx = fmaxf(fmx, pmx_s[r * DC + tid]);
                }
                smid[tid] = (fmx + fmn) * 0.5f;
                sinv[tid] = 1.0f / fmaxf((fmx - fmn) * 0.5f, EPSV);
            }
            __syncthreads();

            const float4 mid = *(const float4*)&smid[4 * j];
            const float4 inv = *(const float4*)&sinv[4 * j];

            // ---- normalize from smem, streaming stores ----
            float* q = y + off;
            #pragma unroll
            for (int k = 0; k < KIT; k++) {
                float4 a = tb[k * NT + tid];
                float4 o;
                o.x = (a.x - mid.x) * inv.x;
                o.y = (a.y - mid.y) * inv.y;
                o.z = (a.z - mid.z) * inv.z;
                o.w = (a.w - mid.w) * inv.w;
                __stcs((float4*)(q + (size_t)k * RB * D_DIM), o);
            }
        } else if (nr_cur > 0) {
            // ---------------- generic path (not hit by dataset) ------------
            const float* xg = x + off;
            float*       yg = y + off;
            float4 mn = make_float4( 3.402823466e38f,  3.402823466e38f,
                                     3.402823466e38f,  3.402823466e38f);
            float4 mx = make_float4(-3.402823466e38f, -3.402823466e38f,
                                    -3.402823466e38f, -3.402823466e38f);
            for (int r = rb; r < nr_cur; r += RB) {
                float4 a = *(const float4*)(xg + (size_t)(r - rb) * D_DIM);
                mn = min4(mn, a);
                mx = max4(mx, a);
            }
            *(float4*)&pmn_s[rb * DC + 4 * j] = mn;
            *(float4*)&pmx_s[rb * DC + 4 * j] = mx;
            __syncthreads();
            if (tid < DC) {
                float fmn = pmn_s[tid];
                float fmx = pmx_s[tid];
                #pragma unroll
                for (int r = 1; r < RB; r++) {
                    fmn = fminf(fmn, pmn_s[r * DC + tid]);
                    fmx = fmaxf(fmx, pmx_s[r * DC + tid]);
                }
                smid[tid] = (fmx + fmn) * 0.5f;
                sinv[tid] = 1.0f / fmaxf((fmx - fmn) * 0.5f, EPSV);
            }
            __syncthreads();
            const float4 mid = *(const float4*)&smid[4 * j];
            const float4 inv = *(const float4*)&sinv[4 * j];
            for (int r = rb; r < nr_cur; r += RB) {
                float4 a = *(const float4*)(xg + (size_t)(r - rb) * D_DIM);
                float4 o;
                o.x = (a.x - mid.x) * inv.x;
                o.y = (a.y - mid.y) * inv.y;
                o.z = (a.z - mid.z) * inv.z;
                o.w = (a.w - mid.w) * inv.w;
                *(float4*)(yg + (size_t)(r - rb) * D_DIM) = o;
            }
            __syncthreads();   // protect smem across iterations
        }

        // ---- advance pipeline ----
        fast   = nfast;
        nr_cur = nnr;
        off    = noff;
        t      = tn;
        it++;
    }
}

// ---------------------------------------------------------------------------
extern "C" void kernel_launch(void* const* d_in, const int* in_sizes, int n_in,
                              void* d_out, int out_size) {
    const float* x  = (const float*)d_in[0];
    const int*   bl = (const int*)d_in[1];
    float*       y  = (float*)d_out;

    const int nb   = in_sizes[1];
    const int ntot = in_sizes[0] / D_DIM;

    offsets_kernel<<<1, 1024>>>(bl, nb, ntot);

    int nbc = nb < MAXB ? nb : MAXB;
    if (nbc < 1) nbc = 1;
    const int ntiles = NCHUNK * nbc;

    // smem: 2 tile buffers + partials + stats
    const int smem = 2 * TILE4 * 16 + 2 * RB * DC * 4 + 2 * DC * 4; // 138,720 B
    cudaFuncSetAttribute(cube_norm_kernel,
                         cudaFuncAttributeMaxDynamicSharedMemorySize, smem);

    int sms = 148;
    cudaDeviceGetAttribute(&sms, cudaDevAttrMultiProcessorCount, 0);
    int grid = sms;                       // persistent: 1 CTA per SM
    if (grid > ntiles) grid = ntiles;

    cube_norm_kernel<<<grid, NT, smem>>>(x, y, ntiles);
}

// round 10
// speedup vs baseline: 1.0935x; 1.0935x over previous
#include <cuda_runtime.h>
#include <cstdint>

// ---------------------------------------------------------------------------
// Problem constants. Dataset: 1024 graphs x 256 rows x 300 cols fp32.
// Fast path (uniform 256-row graphs): cluster(2) kernel, zero-waste aligned
// tiles. Any other batch_list: proven chunked fallback kernel.
// ---------------------------------------------------------------------------
#define D_DIM   300
#define NQ      75            // float4 quads per row
#define GROWS   256           // rows per graph (fast path)
#define HROWS   128           // rows per half-graph
#define KH      16            // float4 per thread in cluster kernel
#define NTC     640           // cluster kernel threads (600 active)
#define ACT     600
#define EPSV    1e-12f

// fallback kernel geometry (the proven R3 config)
#define DC      60
#define DC4     15
#define NCHUNK  5
#define RB      32
#define NT      480
#define KIT     8
#define MAXB    8192

// Scratch (no cudaMalloc allowed).
__device__ int g_off[MAXB + 1];
__device__ int g_B;
__device__ int g_u256;         // 1 iff all graphs have exactly 256 rows

// ---------------------------------------------------------------------------
// Offsets kernel: detects int32 vs int64 batch_list layout; uniform fast path;
// general inclusive scan fallback. Sets g_u256.
// ---------------------------------------------------------------------------
__global__ void offsets_kernel(const int* __restrict__ p32, int nb, int ntot) {
    __shared__ int sh[1024];
    __shared__ int s_stride, s_carry, s_uni, s_val;
    const int tid = threadIdx.x;

    if (tid == 0) {
        int stride = 1;
        if (nb > 1) {
            int v0 = p32[0], v1 = p32[1];
            if (v1 == 0 && v0 != 0) stride = 2;   // int64 little-endian
        }
        s_stride = stride;
        s_carry = 0;
        s_uni = 1;
        s_val = p32[0];
        g_off[0] = 0;
        g_u256 = 0;
    }
    __syncthreads();

    const int st = s_stride;
    int B = nb;
    if (B > MAXB) B = MAXB;
    const int B1 = (st == 2) ? (B >> 1) : B;
    const int v0 = s_val;

    int uni = 1;
    for (int i = tid; i < B1; i += 1024)
        if (p32[(size_t)i * st] != v0) uni = 0;
    if (!uni) atomicAnd(&s_uni, 0);
    __syncthreads();

    if (s_uni && (long long)B1 * v0 == ntot) {
        for (int i = tid; i < B1; i += 1024)
            g_off[i + 1] = (i + 1) * v0;
        if (tid == 0) {
            g_B = B1;
            g_u256 = (v0 == GROWS) ? 1 : 0;
        }
        return;
    }

    for (int base = 0; base < B1; base += 1024) {
        int i = base + tid;
        int v = (i < B1) ? p32[(size_t)i * st] : 0;
        sh[tid] = v;
        __syncthreads();
        #pragma unroll
        for (int o = 1; o < 1024; o <<= 1) {
            int t = (tid >= o) ? sh[tid - o] : 0;
            __syncthreads();
            sh[tid] += t;
            __syncthreads();
        }
        if (i < B1) g_off[i + 1] = s_carry + sh[tid];
        __syncthreads();
        if (tid == 0) s_carry += sh[1023];
        __syncthreads();
    }

    int Bfinal = B1;
    if (st == 2 && B1 > 0 && g_off[B1] != ntot && B > B1) {
        for (int base = B1; base < B; base += 1024) {
            int i = base + tid;
            int v = (i < B) ? p32[(size_t)i * st] : 0;
            sh[tid] = v;
            __syncthreads();
            #pragma unroll
            for (int o = 1; o < 1024; o <<= 1) {
                int t = (tid >= o) ? sh[tid - o] : 0;
                __syncthreads();
                sh[tid] += t;
                __syncthreads();
            }
            if (i < B) g_off[i + 1] = s_carry + sh[tid];
            __syncthreads();
            if (tid == 0) s_carry += sh[1023];
            __syncthreads();
        }
        Bfinal = B;
    }
    if (tid == 0) g_B = Bfinal;
}

// ---------------------------------------------------------------------------
// Helpers
// ---------------------------------------------------------------------------
__device__ __forceinline__ float4 min4(float4 a, float4 b) {
    return make_float4(fminf(a.x, b.x), fminf(a.y, b.y),
                       fminf(a.z, b.z), fminf(a.w, b.w));
}
__device__ __forceinline__ float4 max4(float4 a, float4 b) {
    return make_float4(fmaxf(a.x, b.x), fmaxf(a.y, b.y),
                       fmaxf(a.z, b.z), fmaxf(a.w, b.w));
}
__device__ __forceinline__ unsigned my_ctarank() {
    unsigned r;
    asm("mov.u32 %0, %%cluster_ctarank;" : "=r"(r));
    return r;
}
__device__ __forceinline__ float dsmem_ld_f32(const float* sptr, unsigned peer) {
    unsigned l = (unsigned)__cvta_generic_to_shared((void*)sptr);
    unsigned r; float v;
    asm volatile("mapa.shared::cluster.u32 %0, %1, %2;"
                 : "=r"(r) : "r"(l), "r"(peer));
    asm volatile("ld.shared::cluster.f32 %0, [%1];"
                 : "=f"(v) : "r"(r) : "memory");
    return v;
}
#define CLUSTER_SYNC() do { \
    asm volatile("barrier.cluster.arrive.aligned;" ::: "memory"); \
    asm volatile("barrier.cluster.wait.aligned;"   ::: "memory"); \
} while (0)

// ---------------------------------------------------------------------------
// FAST PATH: uniform 256-row graphs. Cluster of 2 CTAs per graph; each CTA
// owns a 128-row x 300-col half (153,600 B, 128B-aligned, zero sector waste,
// zero cross-CTA line sharing). Thread (j=tid%75, rb=tid/75) keeps its 16
// float4 in registers; halves exchange 300-col min/max via DSMEM with one
// cluster.sync per graph (parity-double-buffered stats remove the second).
// Persistent: 74 clusters (148 CTAs) grid-stride over graphs.
// ---------------------------------------------------------------------------
__global__ void __cluster_dims__(2, 1, 1) __launch_bounds__(NTC, 1)
cube_norm_u256(const float* __restrict__ x, float* __restrict__ y, int ngr) {
    __shared__ float4 pmn[8][NQ];        // 9600 B
    __shared__ float4 pmx[8][NQ];        // 9600 B
    __shared__ float  s_min[2][D_DIM];   // parity-buffered published stats
    __shared__ float  s_max[2][D_DIM];
    __shared__ float  s_mid[D_DIM];
    __shared__ float  s_inv[D_DIM];

    if (!g_u256) return;                 // uniform across cluster: safe exit

    const int tid = threadIdx.x;
    const bool act = (tid < ACT);
    const int j  = act ? (tid % NQ) : 0;
    const int rb = act ? (tid / NQ) : 0;
    const unsigned rank = my_ctarank();
    const unsigned peer = rank ^ 1u;
    const int cid = blockIdx.x >> 1;
    const int ncl = gridDim.x >> 1;

    int parity = 0;
    for (int g = cid; g < ngr; g += ncl) {
        const size_t base =
            ((size_t)g * GROWS + (size_t)rank * HROWS + rb) * D_DIM + 4 * j;

        float4 v[KH];
        if (act) {
            const float* p = x + base;
            #pragma unroll
            for (int k = 0; k < KH; k++)
                v[k] = __ldcs((const float4*)(p + k * 8 * D_DIM));

            float4 mn = v[0], mx = v[0];
            #pragma unroll
            for (int k = 1; k < KH; k++) {
                mn = min4(mn, v[k]);
                mx = max4(mx, v[k]);
            }
            pmn[rb][j] = mn;
            pmx[rb][j] = mx;
        }
        __syncthreads();

        // fold 8 row-blocks -> publish this half's 300-col stats
        if (tid < NQ) {
            float4 fmn = pmn[0][tid];
            float4 fmx = pmx[0][tid];
            #pragma unroll
            for (int r = 1; r < 8; r++) {
                fmn = min4(fmn, pmn[r][tid]);
                fmx = max4(fmx, pmx[r][tid]);
            }
            *(float4*)&s_min[parity][4 * tid] = fmn;
            *(float4*)&s_max[parity][4 * tid] = fmx;
        }
        CLUSTER_SYNC();   // own+peer stats published cluster-wide

        // combine with peer half via DSMEM, compute mid/inv
        if (tid < D_DIM) {
            float a  = s_min[parity][tid];
            float b  = s_max[parity][tid];
            float pa = dsmem_ld_f32(&s_min[parity][tid], peer);
            float pb = dsmem_ld_f32(&s_max[parity][tid], peer);
            float mnv = fminf(a, pa);
            float mxv = fmaxf(b, pb);
            s_mid[tid] = (mxv + mnv) * 0.5f;
            s_inv[tid] = 1.0f / fmaxf((mxv - mnv) * 0.5f, EPSV);
        }
        __syncthreads();

        if (act) {
            const float4 mid = *(const float4*)&s_mid[4 * j];
            const float4 inv = *(const float4*)&s_inv[4 * j];
            float* q = y + base;
            #pragma unroll
            for (int k = 0; k < KH; k++) {
                float4 o;
                o.x = (v[k].x - mid.x) * inv.x;
                o.y = (v[k].y - mid.y) * inv.y;
                o.z = (v[k].z - mid.z) * inv.z;
                o.w = (v[k].w - mid.w) * inv.w;
                __stcs((float4*)(q + k * 8 * D_DIM), o);
            }
        }
        parity ^= 1;
    }
    CLUSTER_SYNC();   // don't exit while peer may still DSMEM-read our stats
}

// ---------------------------------------------------------------------------
// FALLBACK (proven R3 kernel): one CTA per (graph, 60-col chunk), register
// tile, in-flight reduce. Runs only when g_u256 == 0.
// ---------------------------------------------------------------------------
__global__ void __launch_bounds__(NT, 2)
cube_norm_generic(const float* __restrict__ x, float* __restrict__ y) {
    __shared__ float4 s_mn[RB][DC4];
    __shared__ float4 s_mx[RB][DC4];

    if (g_u256) return;                 // fast path handled it

    const int g = blockIdx.y;
    if (g >= g_B) return;
    const int c0 = blockIdx.x * DC;
    const int r0 = g_off[g];
    const int nr = g_off[g + 1] - r0;
    if (nr <= 0) return;

    const int tid = threadIdx.x;
    const int j   = tid % DC4;
    const int rb  = tid / DC4;

    const float* xg = x + (size_t)r0 * D_DIM + c0 + 4 * j;
    float*       yg = y + (size_t)r0 * D_DIM + c0 + 4 * j;

    float4 mn = make_float4( 3.402823466e38f,  3.402823466e38f,
                             3.402823466e38f,  3.402823466e38f);
    float4 mx = make_float4(-3.402823466e38f, -3.402823466e38f,
                            -3.402823466e38f, -3.402823466e38f);
    for (int r = rb; r < nr; r += RB) {
        float4 a = *(const float4*)(xg + (size_t)r * D_DIM);
        mn = min4(mn, a);
        mx = max4(mx, a);
    }
    s_mn[rb][j] = mn;
    s_mx[rb][j] = mx;
    __syncthreads();
    #pragma unroll
    for (int s = RB / 2; s >= 1; s >>= 1) {
        if (rb < s) {
            s_mn[rb][j] = min4(s_mn[rb][j], s_mn[rb + s][j]);
            s_mx[rb][j] = max4(s_mx[rb][j], s_mx[rb + s][j]);
        }
        __syncthreads();
    }
    float4 fmn = s_mn[0][j];
    float4 fmx = s_mx[0][j];
    float4 mid = make_float4((fmx.x + fmn.x) * 0.5f, (fmx.y + fmn.y) * 0.5f,
                             (fmx.z + fmn.z) * 0.5f, (fmx.w + fmn.w) * 0.5f);
    float4 inv = make_float4(
        1.0f / fmaxf((fmx.x - fmn.x) * 0.5f, EPSV),
        1.0f / fmaxf((fmx.y - fmn.y) * 0.5f, EPSV),
        1.0f / fmaxf((fmx.z - fmn.z) * 0.5f, EPSV),
        1.0f / fmaxf((fmx.w - fmn.w) * 0.5f, EPSV));
    for (int r = rb; r < nr; r += RB) {
        float4 a = *(const float4*)(xg + (size_t)r * D_DIM);
        float4 o;
        o.x = (a.x - mid.x) * inv.x;
        o.y = (a.y - mid.y) * inv.y;
        o.z = (a.z - mid.z) * inv.z;
        o.w = (a.w - mid.w) * inv.w;
        *(float4*)(yg + (size_t)r * D_DIM) = o;
    }
}

// ---------------------------------------------------------------------------
extern "C" void kernel_launch(void* const* d_in, const int* in_sizes, int n_in,
                              void* d_out, int out_size) {
    const float* x  = (const float*)d_in[0];
    const int*   bl = (const int*)d_in[1];
    float*       y  = (float*)d_out;

    const int nb   = in_sizes[1];
    const int ntot = in_sizes[0] / D_DIM;

    offsets_kernel<<<1, 1024>>>(bl, nb, ntot);

    // fast path: persistent clusters (1 CTA/SM, 2 CTAs per cluster)
    int sms = 148;
    cudaDeviceGetAttribute(&sms, cudaDevAttrMultiProcessorCount, 0);
    int ngr = ntot / GROWS;                 // valid only when g_u256; guarded
    if (ngr < 1) ngr = 1;
    int clusters = sms / 2;
    if (clusters > ngr) clusters = ngr;
    if (clusters < 1) clusters = 1;
    cube_norm_u256<<<2 * clusters, NTC>>>(x, y, ngr);

    // generic fallback (no-ops when g_u256)
    int gy = nb < MAXB ? nb : MAXB;
    if (gy < 1) gy = 1;
    dim3 grid(NCHUNK, gy);
    cube_norm_generic<<<grid, NT>>>(x, y);
}

// round 11
// speedup vs baseline: 1.2564x; 1.1489x over previous
#include <cuda_runtime.h>

// Problem constants (shapes fixed by dataset; code stays correct for any
// batch_list via the offsets kernel + generic path).
#define D_DIM   300          // embedding dim
#define DC      60           // columns per chunk (multiple of 4, divides 300)
#define DC4     (DC / 4)     // 15 float4 per row-chunk
#define NCHUNK  (D_DIM / DC) // 5
#define TR      256          // row tile (== nodes per graph in this dataset)
#define NT      480          // threads per CTA = 32 row-blocks * 15 col-quads
#define RB      32           // row-blocks
#define KIT     (TR / RB)    // 8 rows per thread in fast path
#define MAXB    8192
#define EPSV    1e-12f

// Scratch (no cudaMalloc allowed): per-graph row offsets + actual graph count.
__device__ int g_off[MAXB + 1];
__device__ int g_B;

// ---------------------------------------------------------------------------
// Offsets kernel: detects int32 vs int64 batch_list layout. Fast path: if all
// counts are equal (dataset case), writes offsets arithmetically with no scan.
// Fallback: block-wide inclusive scan.
// ---------------------------------------------------------------------------
__global__ void offsets_kernel(const int* __restrict__ p32, int nb, int ntot) {
    __shared__ int sh[1024];
    __shared__ int s_stride, s_carry, s_uni, s_val;
    const int tid = threadIdx.x;

    if (tid == 0) {
        int stride = 1;
        if (nb > 1) {
            int v0 = p32[0], v1 = p32[1];
            if (v1 == 0 && v0 != 0) stride = 2;   // int64 little-endian
        }
        s_stride = stride;
        s_carry = 0;
        s_uni = 1;
        s_val = p32[0];
        g_off[0] = 0;
    }
    __syncthreads();

    const int st = s_stride;
    int B = nb;
    if (B > MAXB) B = MAXB;
    const int B1 = (st == 2) ? (B >> 1) : B;
    const int v0 = s_val;

    int uni = 1;
    for (int i = tid; i < B1; i += 1024)
        if (p32[(size_t)i * st] != v0) uni = 0;
    if (!uni) atomicAnd(&s_uni, 0);
    __syncthreads();

    if (s_uni && (long long)B1 * v0 == ntot) {
        for (int i = tid; i < B1; i += 1024)
            g_off[i + 1] = (i + 1) * v0;
        if (tid == 0) g_B = B1;
        return;
    }

    for (int base = 0; base < B1; base += 1024) {
        int i = base + tid;
        int v = (i < B1) ? p32[(size_t)i * st] : 0;
        sh[tid] = v;
        __syncthreads();
        #pragma unroll
        for (int o = 1; o < 1024; o <<= 1) {
            int t = (tid >= o) ? sh[tid - o] : 0;
            __syncthreads();
            sh[tid] += t;
            __syncthreads();
        }
        if (i < B1) g_off[i + 1] = s_carry + sh[tid];
        __syncthreads();
        if (tid == 0) s_carry += sh[1023];
        __syncthreads();
    }

    int Bfinal = B1;
    if (st == 2 && B1 > 0 && g_off[B1] != ntot && B > B1) {
        for (int base = B1; base < B; base += 1024) {
            int i = base + tid;
            int v = (i < B) ? p32[(size_t)i * st] : 0;
            sh[tid] = v;
            __syncthreads();
            #pragma unroll
            for (int o = 1; o < 1024; o <<= 1) {
                int t = (tid >= o) ? sh[tid - o] : 0;
                __syncthreads();
                sh[tid] += t;
                __syncthreads();
            }
            if (i < B) g_off[i + 1] = s_carry + sh[tid];
            __syncthreads();
            if (tid == 0) s_carry += sh[1023];
            __syncthreads();
        }
        Bfinal = B;
    }
    if (tid == 0) g_B = Bfinal;
}

// ---------------------------------------------------------------------------
// Helpers
// ---------------------------------------------------------------------------
__device__ __forceinline__ float4 min4(float4 a, float4 b) {
    return make_float4(fminf(a.x, b.x), fminf(a.y, b.y),
                       fminf(a.z, b.z), fminf(a.w, b.w));
}
__device__ __forceinline__ float4 max4(float4 a, float4 b) {
    return make_float4(fmaxf(a.x, b.x), fmaxf(a.y, b.y),
                       fmaxf(a.z, b.z), fmaxf(a.w, b.w));
}

// ---------------------------------------------------------------------------
// Main kernel (R3 core, default cache policy): one CTA per (graph, 60-col
// chunk). Thread (rb = tid/15, j = tid%15) loads rows rb+32k of column-quad j
// into registers (MLP=8), reducing min/max in flight. Default .ca loads /
// write-back stores: chunk-boundary 128B lines shared by the (concurrently
// resident) adjacent-chunk CTA of the same graph hit in L2 on the second
// touch, and partial-line stores merge in L2 — recovering the ~13% sector
// waste that streaming hints were discarding. Single DRAM read + write.
// ---------------------------------------------------------------------------
__global__ void __launch_bounds__(NT, 2)
cube_norm_kernel(const float* __restrict__ x, float* __restrict__ y) {
    __shared__ float4 s_mn[RB][DC4];   // 15360 B total for both
    __shared__ float4 s_mx[RB][DC4];

    const int g = blockIdx.y;
    if (g >= g_B) return;
    const int c0 = blockIdx.x * DC;
    const int r0 = g_off[g];
    const int nr = g_off[g + 1] - r0;
    if (nr <= 0) return;

    const int tid = threadIdx.x;
    const int j   = tid % DC4;         // column quad 0..14
    const int rb  = tid / DC4;         // row block 0..31

    const float* xg = x + (size_t)r0 * D_DIM + c0 + 4 * j;
    float*       yg = y + (size_t)r0 * D_DIM + c0 + 4 * j;

    if (nr == TR) {
        // ---------------- fast register-resident path ----------------
        float4 v[KIT];
        const float* p = xg + (size_t)rb * D_DIM;
        #pragma unroll
        for (int k = 0; k < KIT; k++)
            v[k] = *(const float4*)(p + (size_t)k * RB * D_DIM);

        float4 mn = v[0], mx = v[0];
        #pragma unroll
        for (int k = 1; k < KIT; k++) {
            mn = min4(mn, v[k]);
            mx = max4(mx, v[k]);
        }
        s_mn[rb][j] = mn;
        s_mx[rb][j] = mx;
        __syncthreads();

        // tree reduce over row blocks
        #pragma unroll
        for (int s = RB / 2; s >= 1; s >>= 1) {
            if (rb < s) {
                s_mn[rb][j] = min4(s_mn[rb][j], s_mn[rb + s][j]);
                s_mx[rb][j] = max4(s_mx[rb][j], s_mx[rb + s][j]);
            }
            __syncthreads();
        }

        float4 fmn = s_mn[0][j];
        float4 fmx = s_mx[0][j];
        float4 mid = make_float4((fmx.x + fmn.x) * 0.5f, (fmx.y + fmn.y) * 0.5f,
                                 (fmx.z + fmn.z) * 0.5f, (fmx.w + fmn.w) * 0.5f);
        float4 inv = make_float4(
            1.0f / fmaxf((fmx.x - fmn.x) * 0.5f, EPSV),
            1.0f / fmaxf((fmx.y - fmn.y) * 0.5f, EPSV),
            1.0f / fmaxf((fmx.z - fmn.z) * 0.5f, EPSV),
            1.0f / fmaxf((fmx.w - fmn.w) * 0.5f, EPSV));

        float* q = yg + (size_t)rb * D_DIM;
        #pragma unroll
        for (int k = 0; k < KIT; k++) {
            float4 o;
            o.x = (v[k].x - mid.x) * inv.x;
            o.y = (v[k].y - mid.y) * inv.y;
            o.z = (v[k].z - mid.z) * inv.z;
            o.w = (v[k].w - mid.w) * inv.w;
            *(float4*)(q + (size_t)k * RB * D_DIM) = o;
        }
    } else {
        // ---------------- generic two-sweep path (not hit by dataset) ------
        float4 mn = make_float4( 3.402823466e38f,  3.402823466e38f,
                                 3.402823466e38f,  3.402823466e38f);
        float4 mx = make_float4(-3.402823466e38f, -3.402823466e38f,
                                -3.402823466e38f, -3.402823466e38f);
        for (int r = rb; r < nr; r += RB) {
            float4 a = *(const float4*)(xg + (size_t)r * D_DIM);
            mn = min4(mn, a);
            mx = max4(mx, a);
        }
        s_mn[rb][j] = mn;
        s_mx[rb][j] = mx;
        __syncthreads();
        #pragma unroll
        for (int s = RB / 2; s >= 1; s >>= 1) {
            if (rb < s) {
                s_mn[rb][j] = min4(s_mn[rb][j], s_mn[rb + s][j]);
                s_mx[rb][j] = max4(s_mx[rb][j], s_mx[rb + s][j]);
            }
            __syncthreads();
        }
        float4 fmn = s_mn[0][j];
        float4 fmx = s_mx[0][j];
        float4 mid = make_float4((fmx.x + fmn.x) * 0.5f, (fmx.y + fmn.y) * 0.5f,
                                 (fmx.z + fmn.z) * 0.5f, (fmx.w + fmn.w) * 0.5f);
        float4 inv = make_float4(
            1.0f / fmaxf((fmx.x - fmn.x) * 0.5f, EPSV),
            1.0f / fmaxf((fmx.y - fmn.y) * 0.5f, EPSV),
            1.0f / fmaxf((fmx.z - fmn.z) * 0.5f, EPSV),
            1.0f / fmaxf((fmx.w - fmn.w) * 0.5f, EPSV));
        for (int r = rb; r < nr; r += RB) {
            float4 a = *(const float4*)(xg + (size_t)r * D_DIM);
            float4 o;
            o.x = (a.x - mid.x) * inv.x;
            o.y = (a.y - mid.y) * inv.y;
            o.z = (a.z - mid.z) * inv.z;
            o.w = (a.w - mid.w) * inv.w;
            *(float4*)(yg + (size_t)r * D_DIM) = o;
        }
    }
}

// ---------------------------------------------------------------------------
extern "C" void kernel_launch(void* const* d_in, const int* in_sizes, int n_in,
                              void* d_out, int out_size) {
    const float* x  = (const float*)d_in[0];
    const int*   bl = (const int*)d_in[1];
    float*       y  = (float*)d_out;

    const int nb   = in_sizes[1];
    const int ntot = in_sizes[0] / D_DIM;

    offsets_kernel<<<1, 1024>>>(bl, nb, ntot);

    int gy = nb < MAXB ? nb : MAXB;
    if (gy < 1) gy = 1;
    dim3 grid(NCHUNK, gy);
    cube_norm_kernel<<<grid, NT>>>(x, y);
}